// round 4
// baseline (speedup 1.0000x reference)
#include <cuda_runtime.h>
#include <cuda_bf16.h>
#include <math.h>

// Problem constants (shapes fixed by the dataset; small slack in buffers)
#define DHID 1024
#define MAXN 10240
#define MAXE 163840
#define NEG_SLOPE 0.1f
#define EPS_V 1e-5f

// ---------------- device scratch ----------------
__device__ float g_h[(size_t)MAXN * DHID];   // h = x @ W
__device__ float g_al[MAXN];
__device__ float g_ar[MAXN];
__device__ int   g_counts[MAXN];
__device__ int   g_cursor[MAXN];
__device__ int   g_offsets[MAXN + 1];
__device__ int   g_src[MAXE];
__device__ int   g_dst[MAXE];
__device__ int   g_dst_sorted[MAXE];
__device__ float g_e_sorted[MAXE];
__device__ int   g_is64;

// ---------------- init: zero counters, set dtype flag ----------------
__global__ void init_kernel(int N) {
    int i = blockIdx.x * blockDim.x + threadIdx.x;
    if (i < N) { g_counts[i] = 0; g_cursor[i] = 0; }
    if (i == 0) g_is64 = 1;
}

// ---------------- detect int32 vs int64 indices ----------------
__global__ void detect_kernel(const void* __restrict__ src, int E, int N) {
    // Read the first chunk as int64. If data is really int32, the combined
    // 8-byte values will be out of [0, N) almost surely.
    int n = E / 2; if (n > 4096) n = 4096;
    for (int k = threadIdx.x; k < n; k += blockDim.x) {
        long long v = ((const long long*)src)[k];
        if (v < 0 || v >= (long long)N) g_is64 = 0;
    }
}

__global__ void convert_kernel(const void* __restrict__ src,
                               const void* __restrict__ dst, int E) {
    int k = blockIdx.x * blockDim.x + threadIdx.x;
    if (k >= E) return;
    int s, d;
    if (g_is64) {
        s = (int)((const long long*)src)[k];
        d = (int)((const long long*)dst)[k];
    } else {
        s = ((const int*)src)[k];
        d = ((const int*)dst)[k];
    }
    g_src[k] = s;
    g_dst[k] = d;
}

// ---------------- GEMM: h = x @ W  (fp32, 128x128x16 tiles, 8x8/thread) ----
#define BM 128
#define BN 128
#define BKK 16

__global__ __launch_bounds__(256)
void gemm_kernel(const float* __restrict__ A,   // [M, 1024]
                 const float* __restrict__ B,   // [1024, 1024]
                 int M) {
    __shared__ float As[BKK][BM];
    __shared__ float Bs[BKK][BN];
    const int K = DHID, NC = DHID;

    int tid = threadIdx.x;
    int tx = tid & 15, ty = tid >> 4;
    int row0 = blockIdx.y * BM;
    int col0 = blockIdx.x * BN;

    float acc[8][8];
#pragma unroll
    for (int i = 0; i < 8; i++)
#pragma unroll
        for (int j = 0; j < 8; j++) acc[i][j] = 0.f;

    float4 pa[2], pb[2];

    // prologue: prefetch tile 0
#pragma unroll
    for (int i = 0; i < 2; i++) {
        int id = tid + i * 256;
        int ar = id >> 2, ak = (id & 3) * 4;
        int grow = row0 + ar;
        pa[i] = (grow < M) ? *(const float4*)&A[(size_t)grow * K + ak]
                           : make_float4(0.f, 0.f, 0.f, 0.f);
        int bk = id >> 5, bc = (id & 31) * 4;
        pb[i] = *(const float4*)&B[(size_t)bk * NC + col0 + bc];
    }

    const int ntiles = K / BKK;
    for (int kt = 0; kt < ntiles; kt++) {
        // store prefetched tile to smem (A transposed)
#pragma unroll
        for (int i = 0; i < 2; i++) {
            int id = tid + i * 256;
            int ar = id >> 2, ak = (id & 3) * 4;
            As[ak + 0][ar] = pa[i].x;
            As[ak + 1][ar] = pa[i].y;
            As[ak + 2][ar] = pa[i].z;
            As[ak + 3][ar] = pa[i].w;
            int bk = id >> 5, bc = (id & 31) * 4;
            *(float4*)&Bs[bk][bc] = pb[i];
        }
        __syncthreads();

        // prefetch next tile while computing on this one
        if (kt + 1 < ntiles) {
            int k0 = (kt + 1) * BKK;
#pragma unroll
            for (int i = 0; i < 2; i++) {
                int id = tid + i * 256;
                int ar = id >> 2, ak = (id & 3) * 4;
                int grow = row0 + ar;
                pa[i] = (grow < M) ? *(const float4*)&A[(size_t)grow * K + k0 + ak]
                                   : make_float4(0.f, 0.f, 0.f, 0.f);
                int bk = id >> 5, bc = (id & 31) * 4;
                pb[i] = *(const float4*)&B[(size_t)(k0 + bk) * NC + col0 + bc];
            }
        }

#pragma unroll
        for (int kk = 0; kk < BKK; kk++) {
            float4 a0 = *(const float4*)&As[kk][ty * 8];
            float4 a1 = *(const float4*)&As[kk][ty * 8 + 4];
            float4 b0 = *(const float4*)&Bs[kk][tx * 8];
            float4 b1 = *(const float4*)&Bs[kk][tx * 8 + 4];
            float ra[8] = {a0.x, a0.y, a0.z, a0.w, a1.x, a1.y, a1.z, a1.w};
            float rb[8] = {b0.x, b0.y, b0.z, b0.w, b1.x, b1.y, b1.z, b1.w};
#pragma unroll
            for (int i = 0; i < 8; i++)
#pragma unroll
                for (int j = 0; j < 8; j++) acc[i][j] += ra[i] * rb[j];
        }
        __syncthreads();
    }

    // epilogue
#pragma unroll
    for (int i = 0; i < 8; i++) {
        int grow = row0 + ty * 8 + i;
        if (grow < M) {
            float4 o0 = make_float4(acc[i][0], acc[i][1], acc[i][2], acc[i][3]);
            float4 o1 = make_float4(acc[i][4], acc[i][5], acc[i][6], acc[i][7]);
            *(float4*)&g_h[(size_t)grow * NC + col0 + tx * 8] = o0;
            *(float4*)&g_h[(size_t)grow * NC + col0 + tx * 8 + 4] = o1;
        }
    }
}

// ---------------- al = h @ a[:D], ar = h @ a[D:]  (one warp / row) --------
__global__ void alar_kernel(const float* __restrict__ a, int N) {
    int warp = (blockIdx.x * blockDim.x + threadIdx.x) >> 5;
    int lane = threadIdx.x & 31;
    if (warp >= N) return;
    const float* hr = &g_h[(size_t)warp * DHID];
    float sl = 0.f, sr = 0.f;
    for (int c = lane * 4; c < DHID; c += 128) {
        float4 hv = *(const float4*)&hr[c];
        float4 av = *(const float4*)&a[c];
        float4 bv = *(const float4*)&a[DHID + c];
        sl += hv.x * av.x + hv.y * av.y + hv.z * av.z + hv.w * av.w;
        sr += hv.x * bv.x + hv.y * bv.y + hv.z * bv.z + hv.w * bv.w;
    }
#pragma unroll
    for (int o = 16; o; o >>= 1) {
        sl += __shfl_xor_sync(0xffffffffu, sl, o);
        sr += __shfl_xor_sync(0xffffffffu, sr, o);
    }
    if (lane == 0) { g_al[warp] = sl; g_ar[warp] = sr; }
}

// ---------------- histogram of src ----------------
__global__ void hist_kernel(int E) {
    int k = blockIdx.x * blockDim.x + threadIdx.x;
    if (k < E) atomicAdd(&g_counts[g_src[k]], 1);
}

// ---------------- exclusive scan (single block) ----------------
__global__ void scan_kernel(int N) {
    __shared__ int sdata[1024];
    __shared__ int carry_s;
    int tid = threadIdx.x;
    if (tid == 0) carry_s = 0;
    __syncthreads();
    for (int base = 0; base < N; base += 1024) {
        int idx = base + tid;
        int v = (idx < N) ? g_counts[idx] : 0;
        sdata[tid] = v;
        __syncthreads();
        for (int off = 1; off < 1024; off <<= 1) {
            int t = (tid >= off) ? sdata[tid - off] : 0;
            __syncthreads();
            sdata[tid] += t;
            __syncthreads();
        }
        int incl = sdata[tid];
        if (idx < N) g_offsets[idx] = carry_s + incl - v;
        int total = sdata[1023];
        __syncthreads();
        if (tid == 0) carry_s += total;
        __syncthreads();
    }
    if (tid == 0) g_offsets[N] = carry_s;
}

// ---------------- edge weights + scatter into src-sorted order ----------
__global__ void scatter_kernel(int E) {
    int k = blockIdx.x * blockDim.x + threadIdx.x;
    if (k >= E) return;
    int s = g_src[k];
    int d = g_dst[k];
    float z = g_al[s] + g_ar[d];
    z = (z > 0.f) ? z : NEG_SLOPE * z;          // leaky_relu
    float ee = expf(-z);
    int pos = g_offsets[s] + atomicAdd(&g_cursor[s], 1);
    g_e_sorted[pos] = ee;
    g_dst_sorted[pos] = d;
}

// ---------------- CSR SpMM + normalize + ELU (one block / row) ----------
__global__ __launch_bounds__(256)
void spmm_kernel(float* __restrict__ out, int N) {
    int row = blockIdx.x;
    if (row >= N) return;
    int tid = threadIdx.x;
    int beg = g_offsets[row];
    int end = g_offsets[row + 1];

    __shared__ float se[256];
    __shared__ int   sd[256];

    float4 acc = make_float4(0.f, 0.f, 0.f, 0.f);
    float rs = 0.f;
    int c = tid * 4;

    for (int base = beg; base < end; base += 256) {
        int nload = end - base;
        if (nload > 256) nload = 256;
        if (tid < nload) {
            se[tid] = g_e_sorted[base + tid];
            sd[tid] = g_dst_sorted[base + tid];
        }
        __syncthreads();
        for (int j = 0; j < nload; j++) {
            float ev = se[j];
            int d = sd[j];
            float4 hv = *(const float4*)&g_h[(size_t)d * DHID + c];
            acc.x += ev * hv.x;
            acc.y += ev * hv.y;
            acc.z += ev * hv.z;
            acc.w += ev * hv.w;
            rs += ev;
        }
        __syncthreads();
    }

    float inv = 1.f / (rs + EPS_V);
    float v0 = acc.x * inv, v1 = acc.y * inv, v2 = acc.z * inv, v3 = acc.w * inv;
    float4 o;
    o.x = (v0 > 0.f) ? v0 : expm1f(v0);
    o.y = (v1 > 0.f) ? v1 : expm1f(v1);
    o.z = (v2 > 0.f) ? v2 : expm1f(v2);
    o.w = (v3 > 0.f) ? v3 : expm1f(v3);
    *(float4*)&out[(size_t)row * DHID + c] = o;
}

// ---------------- launch ----------------
extern "C" void kernel_launch(void* const* d_in, const int* in_sizes, int n_in,
                              void* d_out, int out_size) {
    const float* x = (const float*)d_in[0];
    const float* W = (const float*)d_in[1];
    const float* a = (const float*)d_in[2];
    const void* src = d_in[3];
    const void* dst = d_in[4];
    float* out = (float*)d_out;

    int N = in_sizes[0] / DHID;   // 10000
    int E = in_sizes[3];          // 160000
    if (N > MAXN) N = MAXN;
    if (E > MAXE) E = MAXE;

    init_kernel<<<(N + 255) / 256, 256>>>(N);
    detect_kernel<<<1, 256>>>(src, E, N);
    convert_kernel<<<(E + 255) / 256, 256>>>(src, dst, E);

    dim3 ggrid(DHID / BN, (N + BM - 1) / BM);
    gemm_kernel<<<ggrid, 256>>>(x, W, N);

    alar_kernel<<<(N * 32 + 255) / 256, 256>>>(a, N);

    hist_kernel<<<(E + 255) / 256, 256>>>(E);
    scan_kernel<<<1, 1024>>>(N);
    scatter_kernel<<<(E + 255) / 256, 256>>>(E);

    spmm_kernel<<<N, 256>>>(out, N);
}

// round 7
// speedup vs baseline: 1.8835x; 1.8835x over previous
#include <cuda_runtime.h>
#include <cuda_bf16.h>
#include <math.h>
#include <stdint.h>

#define DHID 1024
#define MAXN 10240
#define MAXE 163840
#define NEG_SLOPE 0.1f
#define EPS_V 1e-5f

// ---------------- device scratch ----------------
__device__ float g_h[(size_t)MAXN * DHID];   // h = x @ W
__device__ float g_al[MAXN];
__device__ float g_ar[MAXN];
__device__ int   g_counts[MAXN];
__device__ int   g_cursor[MAXN];
__device__ int   g_offsets[MAXN + 1];
__device__ int   g_src[MAXE];
__device__ int   g_dst[MAXE];
__device__ int   g_dst_sorted[MAXE];
__device__ float g_e_sorted[MAXE];
__device__ int   g_is64;

__device__ __forceinline__ uint32_t smem_u32(const void* p) {
    uint32_t a;
    asm("{ .reg .u64 t; cvta.to.shared.u64 t, %1; cvt.u32.u64 %0, t; }" : "=r"(a) : "l"(p));
    return a;
}

// ---------------- init ----------------
__global__ void init_kernel(int N) {
    int i = blockIdx.x * blockDim.x + threadIdx.x;
    if (i < N) { g_counts[i] = 0; g_cursor[i] = 0; }
    if (i == 0) g_is64 = 1;
}

__global__ void detect_kernel(const void* __restrict__ src, int E, int N) {
    int n = E / 2; if (n > 4096) n = 4096;
    for (int k = threadIdx.x; k < n; k += blockDim.x) {
        long long v = ((const long long*)src)[k];
        if (v < 0 || v >= (long long)N) g_is64 = 0;
    }
}

__global__ void convert_kernel(const void* __restrict__ src,
                               const void* __restrict__ dst, int E) {
    int k = blockIdx.x * blockDim.x + threadIdx.x;
    if (k >= E) return;
    int s, d;
    if (g_is64) {
        s = (int)((const long long*)src)[k];
        d = (int)((const long long*)dst)[k];
    } else {
        s = ((const int*)src)[k];
        d = ((const int*)dst)[k];
    }
    g_src[k] = s;
    g_dst[k] = d;
}

// ================== tensor-core GEMM via mma.sync (HMMA) ==================
// h = x @ W, split-bf16 (hi*hi + hi*lo + lo*hi), fp32 accum.
// CTA tile 128x128, BK=32. 8 warps, each 64x32 (4x4 m16n8k16 tiles).
#define BM 128
#define BN 128
#define BK 32
#define LDA 40    // As row stride (bf16 elems): conflict-free for ldmatrix
#define LDB 136   // Bs row stride (bf16 elems): conflict-free for ldmatrix.trans

#define AS_ELEMS (BM * LDA)       // 5120
#define BS_ELEMS (BK * LDB)       // 4352
#define SM_AH 0
#define SM_AL (AS_ELEMS * 2)                    // 10240
#define SM_BH (SM_AL + AS_ELEMS * 2)            // 20480
#define SM_BL (SM_BH + BS_ELEMS * 2)            // 29184
#define GEMM_SMEM (SM_BL + BS_ELEMS * 2)        // 37888 bytes (< 48KB default)

__device__ __forceinline__ void mma16816(float* c, const uint32_t* a, const uint32_t* b) {
    asm volatile(
        "mma.sync.aligned.m16n8k16.row.col.f32.bf16.bf16.f32 "
        "{%0,%1,%2,%3}, {%4,%5,%6,%7}, {%8,%9}, {%0,%1,%2,%3};"
        : "+f"(c[0]), "+f"(c[1]), "+f"(c[2]), "+f"(c[3])
        : "r"(a[0]), "r"(a[1]), "r"(a[2]), "r"(a[3]), "r"(b[0]), "r"(b[1]));
}
__device__ __forceinline__ void ldsm4(uint32_t* r, uint32_t addr) {
    asm volatile("ldmatrix.sync.aligned.m8n8.x4.shared.b16 {%0,%1,%2,%3}, [%4];"
                 : "=r"(r[0]), "=r"(r[1]), "=r"(r[2]), "=r"(r[3]) : "r"(addr));
}
__device__ __forceinline__ void ldsm4t(uint32_t* r, uint32_t addr) {
    asm volatile("ldmatrix.sync.aligned.m8n8.x4.trans.shared.b16 {%0,%1,%2,%3}, [%4];"
                 : "=r"(r[0]), "=r"(r[1]), "=r"(r[2]), "=r"(r[3]) : "r"(addr));
}
__device__ __forceinline__ uint2 split_hi(float4 v, float4* rem) {
    __nv_bfloat16 h0 = __float2bfloat16(v.x);
    __nv_bfloat16 h1 = __float2bfloat16(v.y);
    __nv_bfloat16 h2 = __float2bfloat16(v.z);
    __nv_bfloat16 h3 = __float2bfloat16(v.w);
    rem->x = v.x - __bfloat162float(h0);
    rem->y = v.y - __bfloat162float(h1);
    rem->z = v.z - __bfloat162float(h2);
    rem->w = v.w - __bfloat162float(h3);
    uint2 u;
    u.x = (uint32_t)__bfloat16_as_ushort(h0) | ((uint32_t)__bfloat16_as_ushort(h1) << 16);
    u.y = (uint32_t)__bfloat16_as_ushort(h2) | ((uint32_t)__bfloat16_as_ushort(h3) << 16);
    return u;
}
__device__ __forceinline__ uint2 pack_bf16(float4 v) {
    uint2 u;
    u.x = (uint32_t)__bfloat16_as_ushort(__float2bfloat16(v.x)) |
          ((uint32_t)__bfloat16_as_ushort(__float2bfloat16(v.y)) << 16);
    u.y = (uint32_t)__bfloat16_as_ushort(__float2bfloat16(v.z)) |
          ((uint32_t)__bfloat16_as_ushort(__float2bfloat16(v.w)) << 16);
    return u;
}

__global__ __launch_bounds__(256)
void gemm_mma_kernel(const float* __restrict__ A,   // x [M,1024]
                     const float* __restrict__ Bmat,// W [1024,1024]
                     int M) {
    extern __shared__ __align__(16) char sm[];
    uint32_t sbase = smem_u32(sm);

    const int tid = threadIdx.x;
    const int lane = tid & 31;
    const int wid = tid >> 5;
    const int wm = wid & 1;          // 0..1  -> 64-row slab
    const int wn = wid >> 1;         // 0..3  -> 32-col slab
    const int m0 = blockIdx.y * BM;
    const int n0 = blockIdx.x * BN;

    // ldmatrix source addresses (element coords)
    const int lr = (lane & 7) + ((lane >> 3) & 1) * 8;   // 0..15
    const int lc8 = ((lane >> 4) & 1) * 8;               // 0 or 8

    float C[4][4][4];
#pragma unroll
    for (int i = 0; i < 4; i++)
#pragma unroll
        for (int j = 0; j < 4; j++)
#pragma unroll
            for (int q = 0; q < 4; q++) C[i][j][q] = 0.f;

    float4 pa[4], pb[4];
    // prefetch tile 0
#pragma unroll
    for (int i = 0; i < 4; i++) {
        int id = tid + i * 256;
        int ar = id >> 3, ac = (id & 7) * 4;
        int gm = m0 + ar;
        pa[i] = (gm < M) ? *(const float4*)&A[(size_t)gm * DHID + ac]
                         : make_float4(0.f, 0.f, 0.f, 0.f);
        int br = id >> 5, bc = (id & 31) * 4;
        pb[i] = *(const float4*)&Bmat[(size_t)br * DHID + n0 + bc];
    }

    const int NIT = DHID / BK;   // 32
    for (int kt = 0; kt < NIT; kt++) {
        // ---- store prefetched tile to smem (split fp32 -> bf16 hi/lo) ----
#pragma unroll
        for (int i = 0; i < 4; i++) {
            int id = tid + i * 256;
            int ar = id >> 3, ac = (id & 7) * 4;
            float4 rem;
            uint2 uh = split_hi(pa[i], &rem);
            uint2 ul = pack_bf16(rem);
            *(uint2*)(sm + SM_AH + (ar * LDA + ac) * 2) = uh;
            *(uint2*)(sm + SM_AL + (ar * LDA + ac) * 2) = ul;
            int br = id >> 5, bc = (id & 31) * 4;
            uint2 vh = split_hi(pb[i], &rem);
            uint2 vl = pack_bf16(rem);
            *(uint2*)(sm + SM_BH + (br * LDB + bc) * 2) = vh;
            *(uint2*)(sm + SM_BL + (br * LDB + bc) * 2) = vl;
        }
        __syncthreads();

        // ---- prefetch next tile ----
        if (kt + 1 < NIT) {
            int k0 = (kt + 1) * BK;
#pragma unroll
            for (int i = 0; i < 4; i++) {
                int id = tid + i * 256;
                int ar = id >> 3, ac = (id & 7) * 4;
                int gm = m0 + ar;
                pa[i] = (gm < M) ? *(const float4*)&A[(size_t)gm * DHID + k0 + ac]
                                 : make_float4(0.f, 0.f, 0.f, 0.f);
                int br = id >> 5, bc = (id & 31) * 4;
                pb[i] = *(const float4*)&Bmat[(size_t)(k0 + br) * DHID + n0 + bc];
            }
        }

        // ---- compute: 2 k16 steps ----
#pragma unroll
        for (int ks = 0; ks < 2; ks++) {
            uint32_t Ah[4][4], Al[4][4], Bh[4][2], Bl[4][2];
#pragma unroll
            for (int mt = 0; mt < 4; mt++) {
                uint32_t off = ((wm * 64 + mt * 16 + lr) * LDA + ks * 16 + lc8) * 2;
                ldsm4(Ah[mt], sbase + SM_AH + off);
                ldsm4(Al[mt], sbase + SM_AL + off);
            }
#pragma unroll
            for (int nt2 = 0; nt2 < 2; nt2++) {
                uint32_t off = ((ks * 16 + lr) * LDB + wn * 32 + nt2 * 16 + lc8) * 2;
                uint32_t r[4];
                ldsm4t(r, sbase + SM_BH + off);
                Bh[nt2 * 2][0] = r[0]; Bh[nt2 * 2][1] = r[1];
                Bh[nt2 * 2 + 1][0] = r[2]; Bh[nt2 * 2 + 1][1] = r[3];
                ldsm4t(r, sbase + SM_BL + off);
                Bl[nt2 * 2][0] = r[0]; Bl[nt2 * 2][1] = r[1];
                Bl[nt2 * 2 + 1][0] = r[2]; Bl[nt2 * 2 + 1][1] = r[3];
            }
#pragma unroll
            for (int mt = 0; mt < 4; mt++)
#pragma unroll
                for (int nt = 0; nt < 4; nt++) {
                    mma16816(C[mt][nt], Ah[mt], Bh[nt]);
                    mma16816(C[mt][nt], Ah[mt], Bl[nt]);
                    mma16816(C[mt][nt], Al[mt], Bh[nt]);
                }
        }
        __syncthreads();
    }

    // ---- epilogue ----
#pragma unroll
    for (int mt = 0; mt < 4; mt++) {
        int row = m0 + wm * 64 + mt * 16 + (lane >> 2);
#pragma unroll
        for (int nt = 0; nt < 4; nt++) {
            int col = n0 + wn * 32 + nt * 8 + (lane & 3) * 2;
            if (row < M) {
                float2 v = make_float2(C[mt][nt][0], C[mt][nt][1]);
                *(float2*)&g_h[(size_t)row * DHID + col] = v;
            }
            if (row + 8 < M) {
                float2 v = make_float2(C[mt][nt][2], C[mt][nt][3]);
                *(float2*)&g_h[(size_t)(row + 8) * DHID + col] = v;
            }
        }
    }
}

// ---------------- al = h @ a[:D], ar = h @ a[D:]  (one warp / row) --------
__global__ void alar_kernel(const float* __restrict__ a, int N) {
    int warp = (blockIdx.x * blockDim.x + threadIdx.x) >> 5;
    int lane = threadIdx.x & 31;
    if (warp >= N) return;
    const float* hr = &g_h[(size_t)warp * DHID];
    float sl = 0.f, sr = 0.f;
    for (int c = lane * 4; c < DHID; c += 128) {
        float4 hv = *(const float4*)&hr[c];
        float4 av = *(const float4*)&a[c];
        float4 bv = *(const float4*)&a[DHID + c];
        sl += hv.x * av.x + hv.y * av.y + hv.z * av.z + hv.w * av.w;
        sr += hv.x * bv.x + hv.y * bv.y + hv.z * bv.z + hv.w * bv.w;
    }
#pragma unroll
    for (int o = 16; o; o >>= 1) {
        sl += __shfl_xor_sync(0xffffffffu, sl, o);
        sr += __shfl_xor_sync(0xffffffffu, sr, o);
    }
    if (lane == 0) { g_al[warp] = sl; g_ar[warp] = sr; }
}

// ---------------- histogram of src ----------------
__global__ void hist_kernel(int E) {
    int k = blockIdx.x * blockDim.x + threadIdx.x;
    if (k < E) atomicAdd(&g_counts[g_src[k]], 1);
}

// ---------------- exclusive scan (single block) ----------------
__global__ void scan_kernel(int N) {
    __shared__ int sdata[1024];
    __shared__ int carry_s;
    int tid = threadIdx.x;
    if (tid == 0) carry_s = 0;
    __syncthreads();
    for (int base = 0; base < N; base += 1024) {
        int idx = base + tid;
        int v = (idx < N) ? g_counts[idx] : 0;
        sdata[tid] = v;
        __syncthreads();
        for (int off = 1; off < 1024; off <<= 1) {
            int t = (tid >= off) ? sdata[tid - off] : 0;
            __syncthreads();
            sdata[tid] += t;
            __syncthreads();
        }
        int incl = sdata[tid];
        if (idx < N) g_offsets[idx] = carry_s + incl - v;
        int total = sdata[1023];
        __syncthreads();
        if (tid == 0) carry_s += total;
        __syncthreads();
    }
    if (tid == 0) g_offsets[N] = carry_s;
}

// ---------------- edge weights + scatter into src-sorted order ----------
__global__ void scatter_kernel(int E) {
    int k = blockIdx.x * blockDim.x + threadIdx.x;
    if (k >= E) return;
    int s = g_src[k];
    int d = g_dst[k];
    float z = g_al[s] + g_ar[d];
    z = (z > 0.f) ? z : NEG_SLOPE * z;          // leaky_relu
    float ee = expf(-z);
    int pos = g_offsets[s] + atomicAdd(&g_cursor[s], 1);
    g_e_sorted[pos] = ee;
    g_dst_sorted[pos] = d;
}

// ---------------- CSR SpMM + normalize + ELU (one block / row) ----------
__global__ __launch_bounds__(256)
void spmm_kernel(float* __restrict__ out, int N) {
    int row = blockIdx.x;
    if (row >= N) return;
    int tid = threadIdx.x;
    int beg = g_offsets[row];
    int end = g_offsets[row + 1];

    __shared__ float se[256];
    __shared__ int   sd[256];

    float4 acc = make_float4(0.f, 0.f, 0.f, 0.f);
    float rs = 0.f;
    int c = tid * 4;

    for (int base = beg; base < end; base += 256) {
        int nload = end - base;
        if (nload > 256) nload = 256;
        if (tid < nload) {
            se[tid] = g_e_sorted[base + tid];
            sd[tid] = g_dst_sorted[base + tid];
        }
        __syncthreads();
        for (int j = 0; j < nload; j++) {
            float ev = se[j];
            int d = sd[j];
            float4 hv = *(const float4*)&g_h[(size_t)d * DHID + c];
            acc.x += ev * hv.x;
            acc.y += ev * hv.y;
            acc.z += ev * hv.z;
            acc.w += ev * hv.w;
            rs += ev;
        }
        __syncthreads();
    }

    float inv = 1.f / (rs + EPS_V);
    float v0 = acc.x * inv, v1 = acc.y * inv, v2 = acc.z * inv, v3 = acc.w * inv;
    float4 o;
    o.x = (v0 > 0.f) ? v0 : expm1f(v0);
    o.y = (v1 > 0.f) ? v1 : expm1f(v1);
    o.z = (v2 > 0.f) ? v2 : expm1f(v2);
    o.w = (v3 > 0.f) ? v3 : expm1f(v3);
    *(float4*)&out[(size_t)row * DHID + c] = o;
}

// ---------------- launch ----------------
extern "C" void kernel_launch(void* const* d_in, const int* in_sizes, int n_in,
                              void* d_out, int out_size) {
    const float* x = (const float*)d_in[0];
    const float* W = (const float*)d_in[1];
    const float* a = (const float*)d_in[2];
    const void* src = d_in[3];
    const void* dst = d_in[4];
    float* out = (float*)d_out;

    int N = in_sizes[0] / DHID;   // 10000
    int E = in_sizes[3];          // 160000
    if (N > MAXN) N = MAXN;
    if (E > MAXE) E = MAXE;

    init_kernel<<<(N + 255) / 256, 256>>>(N);
    detect_kernel<<<1, 256>>>(src, E, N);
    convert_kernel<<<(E + 255) / 256, 256>>>(src, dst, E);

    dim3 ggrid(DHID / BN, (N + BM - 1) / BM);
    gemm_mma_kernel<<<ggrid, 256, GEMM_SMEM>>>(x, W, N);

    alar_kernel<<<(N * 32 + 255) / 256, 256>>>(a, N);

    hist_kernel<<<(E + 255) / 256, 256>>>(E);
    scan_kernel<<<1, 1024>>>(N);
    scatter_kernel<<<(E + 255) / 256, 256>>>(E);

    spmm_kernel<<<N, 256>>>(out, N);
}

// round 9
// speedup vs baseline: 2.3117x; 1.2274x over previous
#include <cuda_runtime.h>
#include <cuda_bf16.h>
#include <math.h>
#include <stdint.h>

#define DHID 1024
#define MAXN 10240
#define MAXE 163840
#define NEG_SLOPE 0.1f
#define EPS_V 1e-5f

// ---------------- device scratch ----------------
__device__ float g_h[(size_t)MAXN * DHID];   // h = x @ W
__device__ __nv_bfloat16 g_x_hi[(size_t)MAXN * DHID];
__device__ __nv_bfloat16 g_x_lo[(size_t)MAXN * DHID];
__device__ __nv_bfloat16 g_w_hi[DHID * DHID];
__device__ __nv_bfloat16 g_w_lo[DHID * DHID];
__device__ float g_al[MAXN];
__device__ float g_ar[MAXN];
__device__ int   g_counts[MAXN];
__device__ int   g_cursor[MAXN];
__device__ int   g_offsets[MAXN + 1];
__device__ int   g_src[MAXE];
__device__ int   g_dst[MAXE];
__device__ int   g_dst_sorted[MAXE];
__device__ float g_e_sorted[MAXE];
__device__ int   g_is64;

__device__ __forceinline__ uint32_t smem_u32(const void* p) {
    uint32_t a;
    asm("{ .reg .u64 t; cvta.to.shared.u64 t, %1; cvt.u32.u64 %0, t; }" : "=r"(a) : "l"(p));
    return a;
}

__device__ __forceinline__ uint2 split_hi(float4 v, float4* rem) {
    __nv_bfloat16 h0 = __float2bfloat16(v.x);
    __nv_bfloat16 h1 = __float2bfloat16(v.y);
    __nv_bfloat16 h2 = __float2bfloat16(v.z);
    __nv_bfloat16 h3 = __float2bfloat16(v.w);
    rem->x = v.x - __bfloat162float(h0);
    rem->y = v.y - __bfloat162float(h1);
    rem->z = v.z - __bfloat162float(h2);
    rem->w = v.w - __bfloat162float(h3);
    uint2 u;
    u.x = (uint32_t)__bfloat16_as_ushort(h0) | ((uint32_t)__bfloat16_as_ushort(h1) << 16);
    u.y = (uint32_t)__bfloat16_as_ushort(h2) | ((uint32_t)__bfloat16_as_ushort(h3) << 16);
    return u;
}
__device__ __forceinline__ uint2 pack_bf16(float4 v) {
    uint2 u;
    u.x = (uint32_t)__bfloat16_as_ushort(__float2bfloat16(v.x)) |
          ((uint32_t)__bfloat16_as_ushort(__float2bfloat16(v.y)) << 16);
    u.y = (uint32_t)__bfloat16_as_ushort(__float2bfloat16(v.z)) |
          ((uint32_t)__bfloat16_as_ushort(__float2bfloat16(v.w)) << 16);
    return u;
}

// ---------------- init ----------------
__global__ void init_kernel(int N) {
    int i = blockIdx.x * blockDim.x + threadIdx.x;
    if (i < N) { g_counts[i] = 0; g_cursor[i] = 0; }
    if (i == 0) g_is64 = 1;
}

__global__ void detect_kernel(const void* __restrict__ src, int E, int N) {
    int n = E / 2; if (n > 4096) n = 4096;
    for (int k = threadIdx.x; k < n; k += blockDim.x) {
        long long v = ((const long long*)src)[k];
        if (v < 0 || v >= (long long)N) g_is64 = 0;
    }
}

// convert + fused src histogram
__global__ void convert_kernel(const void* __restrict__ src,
                               const void* __restrict__ dst, int E) {
    int k = blockIdx.x * blockDim.x + threadIdx.x;
    if (k >= E) return;
    int s, d;
    if (g_is64) {
        s = (int)((const long long*)src)[k];
        d = (int)((const long long*)dst)[k];
    } else {
        s = ((const int*)src)[k];
        d = ((const int*)dst)[k];
    }
    g_src[k] = s;
    g_dst[k] = d;
    atomicAdd(&g_counts[s], 1);
}

// ---------------- prepass: fp32 -> bf16 hi/lo split ----------------
__global__ void split_kernel(const float4* __restrict__ in,
                             uint2* __restrict__ hi, uint2* __restrict__ lo, int n4) {
    int i = blockIdx.x * blockDim.x + threadIdx.x;
    if (i >= n4) return;
    float4 v = in[i];
    float4 rem;
    uint2 uh = split_hi(v, &rem);
    uint2 ul = pack_bf16(rem);
    hi[i] = uh;
    lo[i] = ul;
}

// ================== tensor-core GEMM via mma.sync (HMMA) ==================
// h = x @ W, split-bf16 (hi*hi + hi*lo + lo*hi), fp32 accum.
// CTA tile 128x128, BK=32, 3-stage cp.async pipeline. 8 warps, 64x32 each.
#define BM 128
#define BN 128
#define BK 32
#define LDA 40    // As row stride (bf16): 80B = 5*16B, conflict-free + aligned
#define LDB 136   // Bs row stride (bf16): 272B = 17*16B

#define OFF_AH 0
#define OFF_AL (BM * LDA * 2)                 // 10240
#define OFF_BH (OFF_AL + BM * LDA * 2)        // 20480
#define OFF_BL (OFF_BH + BK * LDB * 2)        // 29184
#define STG    (OFF_BL + BK * LDB * 2)        // 37888 bytes / stage
#define STAGES 3
#define GEMM_SMEM (STAGES * STG)              // 113664

__device__ __forceinline__ void mma16816(float* c, const uint32_t* a, const uint32_t* b) {
    asm volatile(
        "mma.sync.aligned.m16n8k16.row.col.f32.bf16.bf16.f32 "
        "{%0,%1,%2,%3}, {%4,%5,%6,%7}, {%8,%9}, {%0,%1,%2,%3};"
        : "+f"(c[0]), "+f"(c[1]), "+f"(c[2]), "+f"(c[3])
        : "r"(a[0]), "r"(a[1]), "r"(a[2]), "r"(a[3]), "r"(b[0]), "r"(b[1]));
}
__device__ __forceinline__ void ldsm4(uint32_t* r, uint32_t addr) {
    asm volatile("ldmatrix.sync.aligned.m8n8.x4.shared.b16 {%0,%1,%2,%3}, [%4];"
                 : "=r"(r[0]), "=r"(r[1]), "=r"(r[2]), "=r"(r[3]) : "r"(addr));
}
__device__ __forceinline__ void ldsm4t(uint32_t* r, uint32_t addr) {
    asm volatile("ldmatrix.sync.aligned.m8n8.x4.trans.shared.b16 {%0,%1,%2,%3}, [%4];"
                 : "=r"(r[0]), "=r"(r[1]), "=r"(r[2]), "=r"(r[3]) : "r"(addr));
}
__device__ __forceinline__ void cpa16(uint32_t s, const void* g, int sz) {
    asm volatile("cp.async.cg.shared.global [%0], [%1], 16, %2;"
                 :: "r"(s), "l"(g), "r"(sz) : "memory");
}
#define CP_COMMIT() asm volatile("cp.async.commit_group;" ::: "memory")
#define CP_WAIT1()  asm volatile("cp.async.wait_group 1;" ::: "memory")

__global__ __launch_bounds__(256)
void gemm_mma_kernel(int M) {
    extern __shared__ __align__(16) char sm[];
    uint32_t sbase = smem_u32(sm);

    const int tid = threadIdx.x;
    const int lane = tid & 31;
    const int wid = tid >> 5;
    const int wm = wid & 1;
    const int wn = wid >> 1;
    const int m0 = blockIdx.y * BM;
    const int n0 = blockIdx.x * BN;

    const int lr = (lane & 7) + ((lane >> 3) & 1) * 8;
    const int lc8 = ((lane >> 4) & 1) * 8;

    float C[4][4][4];
#pragma unroll
    for (int i = 0; i < 4; i++)
#pragma unroll
        for (int j = 0; j < 4; j++)
#pragma unroll
            for (int q = 0; q < 4; q++) C[i][j][q] = 0.f;

    // per-thread load coords (2 chunks of 16B per array per stage)
    // A: chunk c -> row c>>2, col (c&3)*8 ; B: chunk c -> row c>>4, col (c&15)*8
    auto issue_load = [&](int kt, int st) {
        int k0 = kt * BK;
        uint32_t sb = sbase + st * STG;
#pragma unroll
        for (int i = 0; i < 2; i++) {
            int c = tid + i * 256;
            int ar = c >> 2, ac = (c & 3) * 8;
            int gm = m0 + ar;
            int sz = (gm < M) ? 16 : 0;
            size_t ga = (size_t)gm * DHID + k0 + ac;
            uint32_t so = (uint32_t)(ar * LDA + ac) * 2;
            cpa16(sb + OFF_AH + so, &g_x_hi[ga], sz);
            cpa16(sb + OFF_AL + so, &g_x_lo[ga], sz);
            int br = c >> 4, bc = (c & 15) * 8;
            size_t gb = (size_t)(k0 + br) * DHID + n0 + bc;
            uint32_t sob = (uint32_t)(br * LDB + bc) * 2;
            cpa16(sb + OFF_BH + sob, &g_w_hi[gb], 16);
            cpa16(sb + OFF_BL + sob, &g_w_lo[gb], 16);
        }
        CP_COMMIT();
    };

    // prologue: stages 0, 1
    issue_load(0, 0);
    issue_load(1, 1);

    const int NIT = DHID / BK;   // 32
    for (int kt = 0; kt < NIT; kt++) {
        CP_WAIT1();
        __syncthreads();

        // issue tile kt+2 into the stage consumed at iter kt-1
        if (kt + 2 < NIT) issue_load(kt + 2, (kt + 2) % STAGES);
        else CP_COMMIT();   // keep group count consistent

        uint32_t sb = sbase + (kt % STAGES) * STG;

#pragma unroll
        for (int ks = 0; ks < 2; ks++) {
            uint32_t Ah[4][4], Al[4][4], Bh[4][2], Bl[4][2];
#pragma unroll
            for (int mt = 0; mt < 4; mt++) {
                uint32_t off = ((wm * 64 + mt * 16 + lr) * LDA + ks * 16 + lc8) * 2;
                ldsm4(Ah[mt], sb + OFF_AH + off);
                ldsm4(Al[mt], sb + OFF_AL + off);
            }
#pragma unroll
            for (int nt2 = 0; nt2 < 2; nt2++) {
                uint32_t off = ((ks * 16 + lr) * LDB + wn * 32 + nt2 * 16 + lc8) * 2;
                uint32_t r[4];
                ldsm4t(r, sb + OFF_BH + off);
                Bh[nt2 * 2][0] = r[0]; Bh[nt2 * 2][1] = r[1];
                Bh[nt2 * 2 + 1][0] = r[2]; Bh[nt2 * 2 + 1][1] = r[3];
                ldsm4t(r, sb + OFF_BL + off);
                Bl[nt2 * 2][0] = r[0]; Bl[nt2 * 2][1] = r[1];
                Bl[nt2 * 2 + 1][0] = r[2]; Bl[nt2 * 2 + 1][1] = r[3];
            }
#pragma unroll
            for (int mt = 0; mt < 4; mt++)
#pragma unroll
                for (int nt = 0; nt < 4; nt++) {
                    mma16816(C[mt][nt], Ah[mt], Bh[nt]);
                    mma16816(C[mt][nt], Ah[mt], Bl[nt]);
                    mma16816(C[mt][nt], Al[mt], Bh[nt]);
                }
        }
        __syncthreads();
    }

    // ---- epilogue ----
#pragma unroll
    for (int mt = 0; mt < 4; mt++) {
        int row = m0 + wm * 64 + mt * 16 + (lane >> 2);
#pragma unroll
        for (int nt = 0; nt < 4; nt++) {
            int col = n0 + wn * 32 + nt * 8 + (lane & 3) * 2;
            if (row < M) {
                float2 v = make_float2(C[mt][nt][0], C[mt][nt][1]);
                *(float2*)&g_h[(size_t)row * DHID + col] = v;
            }
            if (row + 8 < M) {
                float2 v = make_float2(C[mt][nt][2], C[mt][nt][3]);
                *(float2*)&g_h[(size_t)(row + 8) * DHID + col] = v;
            }
        }
    }
}

// ---------------- al = h @ a[:D], ar = h @ a[D:]  (one warp / row) --------
__global__ void alar_kernel(const float* __restrict__ a, int N) {
    int warp = (blockIdx.x * blockDim.x + threadIdx.x) >> 5;
    int lane = threadIdx.x & 31;
    if (warp >= N) return;
    const float* hr = &g_h[(size_t)warp * DHID];
    float sl = 0.f, sr = 0.f;
    for (int c = lane * 4; c < DHID; c += 128) {
        float4 hv = *(const float4*)&hr[c];
        float4 av = *(const float4*)&a[c];
        float4 bv = *(const float4*)&a[DHID + c];
        sl += hv.x * av.x + hv.y * av.y + hv.z * av.z + hv.w * av.w;
        sr += hv.x * bv.x + hv.y * bv.y + hv.z * bv.z + hv.w * bv.w;
    }
#pragma unroll
    for (int o = 16; o; o >>= 1) {
        sl += __shfl_xor_sync(0xffffffffu, sl, o);
        sr += __shfl_xor_sync(0xffffffffu, sr, o);
    }
    if (lane == 0) { g_al[warp] = sl; g_ar[warp] = sr; }
}

// ---------------- exclusive scan (single block) ----------------
__global__ void scan_kernel(int N) {
    __shared__ int sdata[1024];
    __shared__ int carry_s;
    int tid = threadIdx.x;
    if (tid == 0) carry_s = 0;
    __syncthreads();
    for (int base = 0; base < N; base += 1024) {
        int idx = base + tid;
        int v = (idx < N) ? g_counts[idx] : 0;
        sdata[tid] = v;
        __syncthreads();
        for (int off = 1; off < 1024; off <<= 1) {
            int t = (tid >= off) ? sdata[tid - off] : 0;
            __syncthreads();
            sdata[tid] += t;
            __syncthreads();
        }
        int incl = sdata[tid];
        if (idx < N) g_offsets[idx] = carry_s + incl - v;
        int total = sdata[1023];
        __syncthreads();
        if (tid == 0) carry_s += total;
        __syncthreads();
    }
    if (tid == 0) g_offsets[N] = carry_s;
}

// ---------------- edge weights + scatter into src-sorted order ----------
__global__ void scatter_kernel(int E) {
    int k = blockIdx.x * blockDim.x + threadIdx.x;
    if (k >= E) return;
    int s = g_src[k];
    int d = g_dst[k];
    float z = g_al[s] + g_ar[d];
    z = (z > 0.f) ? z : NEG_SLOPE * z;          // leaky_relu
    float ee = expf(-z);
    int pos = g_offsets[s] + atomicAdd(&g_cursor[s], 1);
    g_e_sorted[pos] = ee;
    g_dst_sorted[pos] = d;
}

// ---------------- CSR SpMM + normalize + ELU (one block / row) ----------
__global__ __launch_bounds__(256)
void spmm_kernel(float* __restrict__ out, int N) {
    int row = blockIdx.x;
    if (row >= N) return;
    int tid = threadIdx.x;
    int beg = g_offsets[row];
    int end = g_offsets[row + 1];

    __shared__ float se[256];
    __shared__ int   sd[256];

    float4 acc = make_float4(0.f, 0.f, 0.f, 0.f);
    float rs = 0.f;
    int c = tid * 4;

    for (int base = beg; base < end; base += 256) {
        int nload = end - base;
        if (nload > 256) nload = 256;
        if (tid < nload) {
            se[tid] = g_e_sorted[base + tid];
            sd[tid] = g_dst_sorted[base + tid];
        }
        __syncthreads();
        for (int j = 0; j < nload; j++) {
            float ev = se[j];
            int d = sd[j];
            float4 hv = *(const float4*)&g_h[(size_t)d * DHID + c];
            acc.x += ev * hv.x;
            acc.y += ev * hv.y;
            acc.z += ev * hv.z;
            acc.w += ev * hv.w;
            rs += ev;
        }
        __syncthreads();
    }

    float inv = 1.f / (rs + EPS_V);
    float v0 = acc.x * inv, v1 = acc.y * inv, v2 = acc.z * inv, v3 = acc.w * inv;
    float4 o;
    o.x = (v0 > 0.f) ? v0 : expm1f(v0);
    o.y = (v1 > 0.f) ? v1 : expm1f(v1);
    o.z = (v2 > 0.f) ? v2 : expm1f(v2);
    o.w = (v3 > 0.f) ? v3 : expm1f(v3);
    *(float4*)&out[(size_t)row * DHID + c] = o;
}

// ---------------- launch ----------------
extern "C" void kernel_launch(void* const* d_in, const int* in_sizes, int n_in,
                              void* d_out, int out_size) {
    const float* x = (const float*)d_in[0];
    const float* W = (const float*)d_in[1];
    const float* a = (const float*)d_in[2];
    const void* src = d_in[3];
    const void* dst = d_in[4];
    float* out = (float*)d_out;

    int N = in_sizes[0] / DHID;   // 10000
    int E = in_sizes[3];          // 160000
    if (N > MAXN) N = MAXN;
    if (E > MAXE) E = MAXE;

    init_kernel<<<(N + 255) / 256, 256>>>(N);
    detect_kernel<<<1, 256>>>(src, E, N);
    convert_kernel<<<(E + 255) / 256, 256>>>(src, dst, E);

    // prepass splits
    {
        uint2* xh; uint2* xl; uint2* wh; uint2* wl;
        cudaGetSymbolAddress((void**)&xh, g_x_hi);
        cudaGetSymbolAddress((void**)&xl, g_x_lo);
        cudaGetSymbolAddress((void**)&wh, g_w_hi);
        cudaGetSymbolAddress((void**)&wl, g_w_lo);
        int n4x = N * DHID / 4;
        int n4w = DHID * DHID / 4;
        split_kernel<<<(n4x + 255) / 256, 256>>>((const float4*)x, xh, xl, n4x);
        split_kernel<<<(n4w + 255) / 256, 256>>>((const float4*)W, wh, wl, n4w);
    }

    cudaFuncSetAttribute(gemm_mma_kernel,
                         cudaFuncAttributeMaxDynamicSharedMemorySize, GEMM_SMEM);
    dim3 ggrid(DHID / BN, (N + BM - 1) / BM);
    gemm_mma_kernel<<<ggrid, 256, GEMM_SMEM>>>(N);

    alar_kernel<<<(N * 32 + 255) / 256, 256>>>(a, N);

    scan_kernel<<<1, 1024>>>(N);
    scatter_kernel<<<(E + 255) / 256, 256>>>(E);

    spmm_kernel<<<N, 256>>>(out, N);
}

// round 10
// speedup vs baseline: 2.3574x; 1.0198x over previous
#include <cuda_runtime.h>
#include <cuda_bf16.h>
#include <math.h>
#include <stdint.h>

#define DHID 1024
#define MAXN 10240
#define MAXE 163840
#define NEG_SLOPE 0.1f
#define EPS_V 1e-5f

// ---------------- device scratch ----------------
__device__ float g_h[(size_t)MAXN * DHID];   // h = x @ W
__device__ __nv_bfloat16 g_x_hi[(size_t)MAXN * DHID];
__device__ __nv_bfloat16 g_x_lo[(size_t)MAXN * DHID];
__device__ __nv_bfloat16 g_w_hi[DHID * DHID];
__device__ __nv_bfloat16 g_w_lo[DHID * DHID];
__device__ float g_al[MAXN];
__device__ float g_ar[MAXN];
__device__ int   g_counts[MAXN];
__device__ int   g_cursor[MAXN];
__device__ int   g_offsets[MAXN + 1];
__device__ int   g_src[MAXE];
__device__ int   g_dst[MAXE];
__device__ int   g_dst_sorted[MAXE];
__device__ float g_e_sorted[MAXE];
__device__ int   g_is64;

__device__ __forceinline__ uint32_t smem_u32(const void* p) {
    uint32_t a;
    asm("{ .reg .u64 t; cvta.to.shared.u64 t, %1; cvt.u32.u64 %0, t; }" : "=r"(a) : "l"(p));
    return a;
}

__device__ __forceinline__ uint2 split_hi(float4 v, float4* rem) {
    __nv_bfloat16 h0 = __float2bfloat16(v.x);
    __nv_bfloat16 h1 = __float2bfloat16(v.y);
    __nv_bfloat16 h2 = __float2bfloat16(v.z);
    __nv_bfloat16 h3 = __float2bfloat16(v.w);
    rem->x = v.x - __bfloat162float(h0);
    rem->y = v.y - __bfloat162float(h1);
    rem->z = v.z - __bfloat162float(h2);
    rem->w = v.w - __bfloat162float(h3);
    uint2 u;
    u.x = (uint32_t)__bfloat16_as_ushort(h0) | ((uint32_t)__bfloat16_as_ushort(h1) << 16);
    u.y = (uint32_t)__bfloat16_as_ushort(h2) | ((uint32_t)__bfloat16_as_ushort(h3) << 16);
    return u;
}
__device__ __forceinline__ uint2 pack_bf16(float4 v) {
    uint2 u;
    u.x = (uint32_t)__bfloat16_as_ushort(__float2bfloat16(v.x)) |
          ((uint32_t)__bfloat16_as_ushort(__float2bfloat16(v.y)) << 16);
    u.y = (uint32_t)__bfloat16_as_ushort(__float2bfloat16(v.z)) |
          ((uint32_t)__bfloat16_as_ushort(__float2bfloat16(v.w)) << 16);
    return u;
}

// ---------------- init ----------------
__global__ void init_kernel(int N) {
    int i = blockIdx.x * blockDim.x + threadIdx.x;
    if (i < N) { g_counts[i] = 0; g_cursor[i] = 0; g_al[i] = 0.f; g_ar[i] = 0.f; }
    if (i == 0) g_is64 = 1;
}

__global__ void detect_kernel(const void* __restrict__ src, int E, int N) {
    int n = E / 2; if (n > 4096) n = 4096;
    for (int k = threadIdx.x; k < n; k += blockDim.x) {
        long long v = ((const long long*)src)[k];
        if (v < 0 || v >= (long long)N) g_is64 = 0;
    }
}

// convert + fused src histogram
__global__ void convert_kernel(const void* __restrict__ src,
                               const void* __restrict__ dst, int E) {
    int k = blockIdx.x * blockDim.x + threadIdx.x;
    if (k >= E) return;
    int s, d;
    if (g_is64) {
        s = (int)((const long long*)src)[k];
        d = (int)((const long long*)dst)[k];
    } else {
        s = ((const int*)src)[k];
        d = ((const int*)dst)[k];
    }
    g_src[k] = s;
    g_dst[k] = d;
    atomicAdd(&g_counts[s], 1);
}

// ---------------- prepass: fp32 -> bf16 hi/lo split ----------------
__global__ void split_kernel(const float4* __restrict__ in,
                             uint2* __restrict__ hi, uint2* __restrict__ lo, int n4) {
    int i = blockIdx.x * blockDim.x + threadIdx.x;
    if (i >= n4) return;
    float4 v = in[i];
    float4 rem;
    uint2 uh = split_hi(v, &rem);
    uint2 ul = pack_bf16(rem);
    hi[i] = uh;
    lo[i] = ul;
}

// ================== tensor-core GEMM via mma.sync (HMMA) ==================
// h = x @ W, split-bf16 (hi*hi + hi*lo + lo*hi), fp32 accum.
// CTA tile 128x64, BK=32, 3-stage cp.async pipeline, 2 CTAs/SM.
// 8 warps, each 32x32 (2x4 m16n8k16 tiles). Fused al/ar epilogue.
#define BM 128
#define BN 64
#define BK 32
#define LDA 40    // As row stride (bf16): 80B, conflict-free + 16B aligned
#define LDB 72    // Bs row stride (bf16): 144B

#define OFF_AH 0
#define OFF_AL (BM * LDA * 2)                 // 10240
#define OFF_BH (OFF_AL + BM * LDA * 2)        // 20480
#define OFF_BL (OFF_BH + BK * LDB * 2)        // 25088
#define STG    (OFF_BL + BK * LDB * 2)        // 29696 bytes / stage
#define STAGES 3
#define GEMM_SMEM (STAGES * STG)              // 89088 (x2 CTA = 178K < 228K)

__device__ __forceinline__ void mma16816(float* c, const uint32_t* a, const uint32_t* b) {
    asm volatile(
        "mma.sync.aligned.m16n8k16.row.col.f32.bf16.bf16.f32 "
        "{%0,%1,%2,%3}, {%4,%5,%6,%7}, {%8,%9}, {%0,%1,%2,%3};"
        : "+f"(c[0]), "+f"(c[1]), "+f"(c[2]), "+f"(c[3])
        : "r"(a[0]), "r"(a[1]), "r"(a[2]), "r"(a[3]), "r"(b[0]), "r"(b[1]));
}
__device__ __forceinline__ void ldsm4(uint32_t* r, uint32_t addr) {
    asm volatile("ldmatrix.sync.aligned.m8n8.x4.shared.b16 {%0,%1,%2,%3}, [%4];"
                 : "=r"(r[0]), "=r"(r[1]), "=r"(r[2]), "=r"(r[3]) : "r"(addr));
}
__device__ __forceinline__ void ldsm4t(uint32_t* r, uint32_t addr) {
    asm volatile("ldmatrix.sync.aligned.m8n8.x4.trans.shared.b16 {%0,%1,%2,%3}, [%4];"
                 : "=r"(r[0]), "=r"(r[1]), "=r"(r[2]), "=r"(r[3]) : "r"(addr));
}
__device__ __forceinline__ void cpa16(uint32_t s, const void* g, int sz) {
    asm volatile("cp.async.cg.shared.global [%0], [%1], 16, %2;"
                 :: "r"(s), "l"(g), "r"(sz) : "memory");
}
#define CP_COMMIT() asm volatile("cp.async.commit_group;" ::: "memory")
#define CP_WAIT2()  asm volatile("cp.async.wait_group 2;" ::: "memory")

__global__ __launch_bounds__(256, 2)
void gemm_mma_kernel(const float* __restrict__ avec, int M) {
    extern __shared__ __align__(16) char sm[];
    uint32_t sbase = smem_u32(sm);

    const int tid = threadIdx.x;
    const int lane = tid & 31;
    const int wid = tid >> 5;
    const int wm = wid & 3;          // 0..3 -> 32-row slab
    const int wn = wid >> 2;         // 0..1 -> 32-col slab
    const int m0 = blockIdx.y * BM;
    const int n0 = blockIdx.x * BN;

    const int lr = (lane & 7) + ((lane >> 3) & 1) * 8;
    const int lc8 = ((lane >> 4) & 1) * 8;

    float C[2][4][4];
#pragma unroll
    for (int i = 0; i < 2; i++)
#pragma unroll
        for (int j = 0; j < 4; j++)
#pragma unroll
            for (int q = 0; q < 4; q++) C[i][j][q] = 0.f;

    // A: 512 chunks of 16B (2/thread): chunk c -> row c>>2, col (c&3)*8
    // B: 256 chunks of 16B (1/thread): chunk c -> row c>>3, col (c&7)*8
    auto issue_load = [&](int kt, int st) {
        int k0 = kt * BK;
        uint32_t sb = sbase + st * STG;
#pragma unroll
        for (int i = 0; i < 2; i++) {
            int c = tid + i * 256;
            int ar = c >> 2, ac = (c & 3) * 8;
            int gm = m0 + ar;
            int sz = (gm < M) ? 16 : 0;
            size_t ga = (size_t)gm * DHID + k0 + ac;
            uint32_t so = (uint32_t)(ar * LDA + ac) * 2;
            cpa16(sb + OFF_AH + so, &g_x_hi[ga], sz);
            cpa16(sb + OFF_AL + so, &g_x_lo[ga], sz);
        }
        {
            int br = tid >> 3, bc = (tid & 7) * 8;
            size_t gb = (size_t)(k0 + br) * DHID + n0 + bc;
            uint32_t sob = (uint32_t)(br * LDB + bc) * 2;
            cpa16(sb + OFF_BH + sob, &g_w_hi[gb], 16);
            cpa16(sb + OFF_BL + sob, &g_w_lo[gb], 16);
        }
        CP_COMMIT();
    };

    issue_load(0, 0);
    issue_load(1, 1);

    const int NIT = DHID / BK;   // 32
    for (int kt = 0; kt < NIT; kt++) {
        // issue tile kt+2 into stage freed at end of iter kt-1
        if (kt + 2 < NIT) issue_load(kt + 2, (kt + 2) % STAGES);
        else CP_COMMIT();
        CP_WAIT2();
        __syncthreads();

        uint32_t sb = sbase + (kt % STAGES) * STG;

#pragma unroll
        for (int ks = 0; ks < 2; ks++) {
            uint32_t Ah[2][4], Al[2][4], Bh[4][2], Bl[4][2];
#pragma unroll
            for (int mt = 0; mt < 2; mt++) {
                uint32_t off = ((wm * 32 + mt * 16 + lr) * LDA + ks * 16 + lc8) * 2;
                ldsm4(Ah[mt], sb + OFF_AH + off);
                ldsm4(Al[mt], sb + OFF_AL + off);
            }
#pragma unroll
            for (int nt2 = 0; nt2 < 2; nt2++) {
                uint32_t off = ((ks * 16 + lr) * LDB + wn * 32 + nt2 * 16 + lc8) * 2;
                uint32_t r[4];
                ldsm4t(r, sb + OFF_BH + off);
                Bh[nt2 * 2][0] = r[0]; Bh[nt2 * 2][1] = r[1];
                Bh[nt2 * 2 + 1][0] = r[2]; Bh[nt2 * 2 + 1][1] = r[3];
                ldsm4t(r, sb + OFF_BL + off);
                Bl[nt2 * 2][0] = r[0]; Bl[nt2 * 2][1] = r[1];
                Bl[nt2 * 2 + 1][0] = r[2]; Bl[nt2 * 2 + 1][1] = r[3];
            }
#pragma unroll
            for (int mt = 0; mt < 2; mt++)
#pragma unroll
                for (int nt = 0; nt < 4; nt++) {
                    mma16816(C[mt][nt], Ah[mt], Bh[nt]);
                    mma16816(C[mt][nt], Ah[mt], Bl[nt]);
                    mma16816(C[mt][nt], Al[mt], Bh[nt]);
                }
        }
        __syncthreads();
    }

    // ---- epilogue: store h + fused partial al/ar ----
    // per-thread a values for its 8 columns
    float av_l[8], av_r[8];
#pragma unroll
    for (int nt = 0; nt < 4; nt++) {
        int col = n0 + wn * 32 + nt * 8 + (lane & 3) * 2;
        av_l[nt * 2] = avec[col];       av_l[nt * 2 + 1] = avec[col + 1];
        av_r[nt * 2] = avec[DHID + col]; av_r[nt * 2 + 1] = avec[DHID + col + 1];
    }
#pragma unroll
    for (int mt = 0; mt < 2; mt++) {
        int row = m0 + wm * 32 + mt * 16 + (lane >> 2);
        float pl0 = 0.f, pr0 = 0.f, pl1 = 0.f, pr1 = 0.f;
#pragma unroll
        for (int nt = 0; nt < 4; nt++) {
            int col = n0 + wn * 32 + nt * 8 + (lane & 3) * 2;
            if (row < M) {
                float2 v = make_float2(C[mt][nt][0], C[mt][nt][1]);
                *(float2*)&g_h[(size_t)row * DHID + col] = v;
            }
            if (row + 8 < M) {
                float2 v = make_float2(C[mt][nt][2], C[mt][nt][3]);
                *(float2*)&g_h[(size_t)(row + 8) * DHID + col] = v;
            }
            pl0 += C[mt][nt][0] * av_l[nt * 2] + C[mt][nt][1] * av_l[nt * 2 + 1];
            pr0 += C[mt][nt][0] * av_r[nt * 2] + C[mt][nt][1] * av_r[nt * 2 + 1];
            pl1 += C[mt][nt][2] * av_l[nt * 2] + C[mt][nt][3] * av_l[nt * 2 + 1];
            pr1 += C[mt][nt][2] * av_r[nt * 2] + C[mt][nt][3] * av_r[nt * 2 + 1];
        }
        // reduce over the 4 lanes sharing a row (lane&3 spans cols)
#pragma unroll
        for (int o = 1; o < 4; o <<= 1) {
            pl0 += __shfl_xor_sync(0xffffffffu, pl0, o);
            pr0 += __shfl_xor_sync(0xffffffffu, pr0, o);
            pl1 += __shfl_xor_sync(0xffffffffu, pl1, o);
            pr1 += __shfl_xor_sync(0xffffffffu, pr1, o);
        }
        if ((lane & 3) == 0) {
            if (row < M)     { atomicAdd(&g_al[row], pl0);     atomicAdd(&g_ar[row], pr0); }
            if (row + 8 < M) { atomicAdd(&g_al[row + 8], pl1); atomicAdd(&g_ar[row + 8], pr1); }
        }
    }
}

// ---------------- exclusive scan: 10 elems/thread + shfl block scan ------
__global__ void scan_kernel(int N) {
    __shared__ int warp_tot[32];
    int tid = threadIdx.x;
    int lane = tid & 31, wrp = tid >> 5;
    int base = tid * 10;
    int loc[10];
    int s = 0;
#pragma unroll
    for (int q = 0; q < 10; q++) {
        int idx = base + q;
        int val = (idx < N) ? g_counts[idx] : 0;
        loc[q] = s;
        s += val;
    }
    int inc = s;
#pragma unroll
    for (int o = 1; o < 32; o <<= 1) {
        int t = __shfl_up_sync(0xffffffffu, inc, o);
        if (lane >= o) inc += t;
    }
    if (lane == 31) warp_tot[wrp] = inc;
    __syncthreads();
    if (wrp == 0) {
        int w = warp_tot[lane];
#pragma unroll
        for (int o = 1; o < 32; o <<= 1) {
            int t = __shfl_up_sync(0xffffffffu, w, o);
            if (lane >= o) w += t;
        }
        warp_tot[lane] = w;   // inclusive warp totals
    }
    __syncthreads();
    int warp_off = (wrp > 0) ? warp_tot[wrp - 1] : 0;
    int thr_excl = warp_off + inc - s;
#pragma unroll
    for (int q = 0; q < 10; q++) {
        int idx = base + q;
        if (idx < N) g_offsets[idx] = thr_excl + loc[q];
    }
    if (tid == 1023) g_offsets[N] = thr_excl + s;
}

// ---------------- edge weights + scatter into src-sorted order ----------
__global__ void scatter_kernel(int E) {
    int k = blockIdx.x * blockDim.x + threadIdx.x;
    if (k >= E) return;
    int s = g_src[k];
    int d = g_dst[k];
    float z = g_al[s] + g_ar[d];
    z = (z > 0.f) ? z : NEG_SLOPE * z;          // leaky_relu
    float ee = expf(-z);
    int pos = g_offsets[s] + atomicAdd(&g_cursor[s], 1);
    g_e_sorted[pos] = ee;
    g_dst_sorted[pos] = d;
}

// ---------------- CSR SpMM + normalize + ELU (one block / row) ----------
__global__ __launch_bounds__(256)
void spmm_kernel(float* __restrict__ out, int N) {
    int row = blockIdx.x;
    if (row >= N) return;
    int tid = threadIdx.x;
    int beg = g_offsets[row];
    int end = g_offsets[row + 1];

    __shared__ float se[256];
    __shared__ int   sd[256];

    float4 acc = make_float4(0.f, 0.f, 0.f, 0.f);
    float rs = 0.f;
    int c = tid * 4;

    for (int base = beg; base < end; base += 256) {
        int nload = end - base;
        if (nload > 256) nload = 256;
        if (tid < nload) {
            se[tid] = g_e_sorted[base + tid];
            sd[tid] = g_dst_sorted[base + tid];
        }
        __syncthreads();
        for (int j = 0; j < nload; j++) {
            float ev = se[j];
            int d = sd[j];
            float4 hv = *(const float4*)&g_h[(size_t)d * DHID + c];
            acc.x += ev * hv.x;
            acc.y += ev * hv.y;
            acc.z += ev * hv.z;
            acc.w += ev * hv.w;
            rs += ev;
        }
        __syncthreads();
    }

    float inv = 1.f / (rs + EPS_V);
    float v0 = acc.x * inv, v1 = acc.y * inv, v2 = acc.z * inv, v3 = acc.w * inv;
    float4 o;
    o.x = (v0 > 0.f) ? v0 : expm1f(v0);
    o.y = (v1 > 0.f) ? v1 : expm1f(v1);
    o.z = (v2 > 0.f) ? v2 : expm1f(v2);
    o.w = (v3 > 0.f) ? v3 : expm1f(v3);
    *(float4*)&out[(size_t)row * DHID + c] = o;
}

// ---------------- launch ----------------
extern "C" void kernel_launch(void* const* d_in, const int* in_sizes, int n_in,
                              void* d_out, int out_size) {
    const float* x = (const float*)d_in[0];
    const float* W = (const float*)d_in[1];
    const float* a = (const float*)d_in[2];
    const void* src = d_in[3];
    const void* dst = d_in[4];
    float* out = (float*)d_out;

    int N = in_sizes[0] / DHID;   // 10000
    int E = in_sizes[3];          // 160000
    if (N > MAXN) N = MAXN;
    if (E > MAXE) E = MAXE;

    init_kernel<<<(N + 255) / 256, 256>>>(N);
    detect_kernel<<<1, 256>>>(src, E, N);
    convert_kernel<<<(E + 255) / 256, 256>>>(src, dst, E);
    scan_kernel<<<1, 1024>>>(N);

    // prepass splits
    {
        uint2* xh; uint2* xl; uint2* wh; uint2* wl;
        cudaGetSymbolAddress((void**)&xh, g_x_hi);
        cudaGetSymbolAddress((void**)&xl, g_x_lo);
        cudaGetSymbolAddress((void**)&wh, g_w_hi);
        cudaGetSymbolAddress((void**)&wl, g_w_lo);
        int n4x = N * DHID / 4;
        int n4w = DHID * DHID / 4;
        split_kernel<<<(n4x + 255) / 256, 256>>>((const float4*)x, xh, xl, n4x);
        split_kernel<<<(n4w + 255) / 256, 256>>>((const float4*)W, wh, wl, n4w);
    }

    cudaFuncSetAttribute(gemm_mma_kernel,
                         cudaFuncAttributeMaxDynamicSharedMemorySize, GEMM_SMEM);
    dim3 ggrid(DHID / BN, (N + BM - 1) / BM);
    gemm_mma_kernel<<<ggrid, 256, GEMM_SMEM>>>(a, N);

    scatter_kernel<<<(E + 255) / 256, 256>>>(E);

    spmm_kernel<<<N, 256>>>(out, N);
}